// round 14
// baseline (speedup 1.0000x reference)
#include <cuda_runtime.h>
#include <cstdint>

// QNADE — autoregressive NADE. N=8192, D=64, H=4096, M=2.
// R12 scalar skeleton (proven) + pairwise shared rcp (FMUL->MUFU rebalance) +
// interleaved 2-value shuffle reduction (redux.f32 is NOT sm_103 — compile-checked).
//   acc pre-scaled: acc = 2*log2(e)*(b1 + sum_j x_j W1[j,:])
//   q = 1/(exp2(acc)+1)  (tanh = 1-2q)
//   z = C - 2*dot(q, W2col), C = sum(W2col)+b2 (once)

#define N_SAMP   8192
#define D_SITES  64
#define H_DIM    4096
#define B_SAMP   4
#define THREADS  512
#define HPART    128          // threads per sample
#define PER_THR  32           // h-elements per thread
#define PAD_CH   36           // 32 data + 4 pad words -> conflict-free LDS.128
#define CH       (HPART * PAD_CH)    // 4608 floats per W1 row buffer
#define KTANH    2.8853900817779268f // 2*log2(e)

__device__ __forceinline__ float fex2(float x) {
    float e; asm("ex2.approx.f32 %0, %1;" : "=f"(e) : "f"(x)); return e;
}
__device__ __forceinline__ float frcp(float x) {
    float r; asm("rcp.approx.f32 %0, %1;" : "=f"(r) : "f"(x)); return r;
}
__device__ __forceinline__ void cp16(uint32_t dst, const void* src) {
    asm volatile("cp.async.ca.shared.global [%0], [%1], 16;" :: "r"(dst), "l"(src));
}

__global__ __launch_bounds__(THREADS, 2)
void qnade_kernel(const float* __restrict__ x,
                  const float* __restrict__ W1,
                  const float* __restrict__ b1,
                  const float* __restrict__ W2,
                  const float* __restrict__ b2,
                  float* __restrict__ out)
{
    // smem (floats): W1s[2][CH] | W2xs[CH] | W2ys[CH] | Xs[256] | red[2][16] float2
    extern __shared__ float smem[];
    float*  W1s  = smem;
    float*  W2xs = smem + 2 * CH;
    float*  W2ys = W2xs + CH;
    float*  Xs   = W2ys + CH;
    float2* red  = (float2*)(Xs + B_SAMP * D_SITES);

    const int t    = threadIdx.x;
    const int nl   = t >> 7;        // local sample 0..3
    const int hp   = t & 127;       // h-chunk 0..127 (32 h-values each)
    const int warp = t >> 5;
    const int lane = t & 31;
    const int n0   = blockIdx.x * B_SAMP;
    const bool leader = (hp == 0);
    const uint32_t smem_u32 = (uint32_t)__cvta_generic_to_shared(smem);

    // ---- stage W2 (split, chunk-padded) + spins ----
    const float2* W2g = (const float2*)W2;
    #pragma unroll
    for (int i = t; i < H_DIM; i += THREADS) {
        const float2 g = W2g[i];
        const int c = i >> 5, k = i & 31;
        W2xs[c * PAD_CH + k] = g.x;
        W2ys[c * PAD_CH + k] = g.y;
    }
    if (t < B_SAMP * D_SITES)
        Xs[t] = x[(size_t)n0 * D_SITES + t];

    // ---- stage W1 row 0 into buffer 0 ----
    #pragma unroll
    for (int j = t; j < H_DIM / 4; j += THREADS)
        cp16(smem_u32 + (uint32_t)((j >> 3) * PAD_CH + ((j & 7) << 2)) * 4u, W1 + 4 * j);
    asm volatile("cp.async.commit_group;");

    // ---- acc init: pre-scaled b1 ----
    float acc[PER_THR];
    {
        const float4* b1v = (const float4*)(b1 + hp * PER_THR);
        #pragma unroll
        for (int k = 0; k < 8; k++) {
            const float4 v = b1v[k];
            acc[4 * k + 0] = KTANH * v.x;
            acc[4 * k + 1] = KTANH * v.y;
            acc[4 * k + 2] = KTANH * v.z;
            acc[4 * k + 3] = KTANH * v.w;
        }
    }

    asm volatile("cp.async.wait_group 0;" ::: "memory");
    __syncthreads();   // W2/Xs/W1row0 visible

    const float* WXb = W2xs + hp * PAD_CH;
    const float* WYb = W2ys + hp * PAD_CH;

    // ---- one-time C0/C1 = sum(W2 col) + b2 ----
    float C0 = 0.0f, C1 = 0.0f;
    {
        float sx = 0.0f, sy = 0.0f;
        const float4* wx4 = (const float4*)WXb;
        const float4* wy4 = (const float4*)WYb;
        #pragma unroll
        for (int k = 0; k < 8; k++) {
            const float4 a = wx4[k], bq = wy4[k];
            sx += (a.x + a.y) + (a.z + a.w);
            sy += (bq.x + bq.y) + (bq.z + bq.w);
        }
        #pragma unroll
        for (int o = 16; o; o >>= 1) {
            sx += __shfl_xor_sync(0xffffffffu, sx, o);
            sy += __shfl_xor_sync(0xffffffffu, sy, o);
        }
        if (lane == 0) red[warp] = make_float2(sx, sy);
        __syncthreads();
        if (leader) {
            float a0s = 0.0f, a1s = 0.0f;
            #pragma unroll
            for (int w = 0; w < 4; w++) {
                const float2 v = red[nl * 4 + w];
                a0s += v.x; a1s += v.y;
            }
            C0 = a0s + b2[0];
            C1 = a1s + b2[1];
        }
        __syncthreads();   // red free for the main loop
    }

    float wav = 1.0f;
    int buf = 0;

    for (int d = 0; d < D_SITES; d++) {
        // prefetch W1 row d+1 into the other buffer
        if (d + 1 < D_SITES) {
            const float* src = W1 + (size_t)(d + 1) * H_DIM;
            const uint32_t dbase = smem_u32 + (uint32_t)((buf ^ 1) * CH) * 4u;
            #pragma unroll
            for (int j = t; j < H_DIM / 4; j += THREADS)
                cp16(dbase + (uint32_t)((j >> 3) * PAD_CH + ((j & 7) << 2)) * 4u, src + 4 * j);
        }
        asm volatile("cp.async.commit_group;");

        const float xs = Xs[nl * D_SITES + d];
        const float cx = KTANH * xs;
        const float* W1b = W1s + buf * CH + hp * PAD_CH;

        // two accumulators per output column to shorten FFMA chains
        float d0a = 0.0f, d0b = 0.0f, d1a = 0.0f, d1b = 0.0f;

        #pragma unroll
        for (int q = 0; q < 8; q++) {
            const float4 w1 = *(const float4*)(W1b + 4 * q);
            const float4 wx = *(const float4*)(WXb + 4 * q);
            const float4 wy = *(const float4*)(WYb + 4 * q);
            const float s0 = acc[4 * q + 0];
            const float s1 = acc[4 * q + 1];
            const float s2 = acc[4 * q + 2];
            const float s3 = acc[4 * q + 3];
            const float u0 = fex2(s0) + 1.0f;
            const float u1 = fex2(s1) + 1.0f;
            const float u2 = fex2(s2) + 1.0f;
            const float u3 = fex2(s3) + 1.0f;
            // pairwise shared rcp: 3 FMUL + 1 MUFU per pair
            const float rA = frcp(u0 * u1);
            const float q0 = rA * u1;
            const float q1 = rA * u0;
            const float rB = frcp(u2 * u3);
            const float q2 = rB * u3;
            const float q3 = rB * u2;
            d0a = fmaf(q0, wx.x, d0a);
            d0b = fmaf(q1, wx.y, d0b);
            d0a = fmaf(q2, wx.z, d0a);
            d0b = fmaf(q3, wx.w, d0b);
            d1a = fmaf(q0, wy.x, d1a);
            d1b = fmaf(q1, wy.y, d1b);
            d1a = fmaf(q2, wy.z, d1a);
            d1b = fmaf(q3, wy.w, d1b);
            acc[4 * q + 0] = fmaf(cx, w1.x, s0);
            acc[4 * q + 1] = fmaf(cx, w1.y, s1);
            acc[4 * q + 2] = fmaf(cx, w1.z, s2);
            acc[4 * q + 3] = fmaf(cx, w1.w, s3);
        }
        float D0 = d0a + d0b;
        float D1 = d1a + d1b;

        // interleaved 2-value reduction: even lanes accumulate D0, odd D1.
        const float e0 = __shfl_xor_sync(0xffffffffu, D0, 1);
        const float e1 = __shfl_xor_sync(0xffffffffu, D1, 1);
        float v = (lane & 1) ? (D1 + e1) : (D0 + e0);
        #pragma unroll
        for (int o = 2; o < 32; o <<= 1)
            v += __shfl_xor_sync(0xffffffffu, v, o);
        const float vo = __shfl_xor_sync(0xffffffffu, v, 1);  // lane0: D1 total

        float2* redb = red + (d & 1) * 16;
        if (lane == 0) redb[warp] = make_float2(v, vo);

        asm volatile("cp.async.wait_group 0;" ::: "memory");
        __syncthreads();   // publishes red AND next W1 buffer

        if (leader) {
            const float2 r0 = redb[nl * 4 + 0];
            const float2 r1 = redb[nl * 4 + 1];
            const float2 r2 = redb[nl * 4 + 2];
            const float2 r3 = redb[nl * 4 + 3];
            const float S0 = (r0.x + r1.x) + (r2.x + r3.x);
            const float S1 = (r0.y + r1.y) + (r2.y + r3.y);
            const float z0 = fmaf(-2.0f, S0, C0);
            const float z1 = fmaf(-2.0f, S1, C1);
            const float t0 = tanhf(z0), t1 = tanhf(z1);
            const float nrm = fmaxf(sqrtf(t0 * t0 + t1 * t1), 1e-12f);
            wav *= (xs > 0.0f ? t0 : t1) / nrm;
        }
        buf ^= 1;
    }

    if (leader) out[n0 + nl] = wav;
}

extern "C" void kernel_launch(void* const* d_in, const int* in_sizes, int n_in,
                              void* d_out, int out_size) {
    const float* x  = (const float*)d_in[0];   // [8192,64]
    const float* W1 = (const float*)d_in[1];   // [64,4096]
    const float* b1 = (const float*)d_in[2];   // [4096]
    const float* W2 = (const float*)d_in[3];   // [4096,2]
    const float* b2 = (const float*)d_in[4];   // [2]
    float* out = (float*)d_out;                // [8192]

    const int smem_bytes =
        (4 * CH + B_SAMP * D_SITES) * (int)sizeof(float) + 32 * (int)sizeof(float2);

    cudaFuncSetAttribute(qnade_kernel,
                         cudaFuncAttributeMaxDynamicSharedMemorySize, smem_bytes);

    qnade_kernel<<<N_SAMP / B_SAMP, THREADS, smem_bytes>>>(x, W1, b1, W2, b2, out);
}

// round 15
// speedup vs baseline: 1.0402x; 1.0402x over previous
#include <cuda_runtime.h>
#include <cstdint>

// QNADE — autoregressive NADE. N=8192, D=64, H=4096, M=2.
// KEY CHANGE vs R12: spins are +-1, so exp2(acc) evolves MULTIPLICATIVELY via a
// precomputed table E+-[d,h] = exp2(+-2log2(e)*W1[d,h]). The inner-loop ex2 (MUFU,
// the hidden co-binding pipe per R14's alu-line experiment) is eliminated;
// {ex2 + acc FFMA} -> one FMUL. Sign choice is a per-site POINTER select.
//   e = exp2(2log2e*(b1 + sum_j x_j W1[j,:]))   (multiplicative running state)
//   q = 1/(e+1)  (tanh = 1-2q), pairwise shared rcp
//   z = C - 2*dot(q, W2col), C = sum(W2col)+b2 (once)

#define N_SAMP   8192
#define D_SITES  64
#define H_DIM    4096
#define B_SAMP   4
#define THREADS  512
#define HPART    128          // threads per sample
#define PER_THR  32           // h-elements per thread
#define PAD_CH   36           // 32 data + 4 pad words -> conflict-free LDS.128
#define CH       (HPART * PAD_CH)    // 4608 floats per staged row
#define KTANH    2.8853900817779268f // 2*log2(e)

__device__ float g_Ep[D_SITES * H_DIM];   // exp2(+K*W1)
__device__ float g_Em[D_SITES * H_DIM];   // exp2(-K*W1)

__global__ void qnade_prep(const float* __restrict__ W1) {
    const int i = blockIdx.x * blockDim.x + threadIdx.x;   // 0 .. 262143
    const float w = KTANH * W1[i];
    g_Ep[i] = exp2f(w);
    g_Em[i] = exp2f(-w);
}

__device__ __forceinline__ float fex2(float x) {
    float e; asm("ex2.approx.f32 %0, %1;" : "=f"(e) : "f"(x)); return e;
}
__device__ __forceinline__ float frcp(float x) {
    float r; asm("rcp.approx.f32 %0, %1;" : "=f"(r) : "f"(x)); return r;
}
__device__ __forceinline__ void cp16(uint32_t dst, const void* src) {
    asm volatile("cp.async.ca.shared.global [%0], [%1], 16;" :: "r"(dst), "l"(src));
}

__global__ __launch_bounds__(THREADS, 2)
void qnade_kernel(const float* __restrict__ x,
                  const float* __restrict__ b1,
                  const float* __restrict__ W2,
                  const float* __restrict__ b2,
                  float* __restrict__ out)
{
    // smem (floats): Es[2 buffers][Ep row: CH | Em row: CH] = 4*CH
    //              | W2xs[CH] | W2ys[CH] | Xs[256] | red[2][16] float2
    extern __shared__ float smem[];
    float*  Es   = smem;                 // 4*CH
    float*  W2xs = smem + 4 * CH;
    float*  W2ys = W2xs + CH;
    float*  Xs   = W2ys + CH;
    float2* red  = (float2*)(Xs + B_SAMP * D_SITES);

    const int t    = threadIdx.x;
    const int nl   = t >> 7;        // local sample 0..3
    const int hp   = t & 127;       // h-chunk 0..127 (32 h-values each)
    const int warp = t >> 5;
    const int lane = t & 31;
    const int n0   = blockIdx.x * B_SAMP;
    const bool leader = (hp == 0);
    const uint32_t smem_u32 = (uint32_t)__cvta_generic_to_shared(smem);

    // ---- stage W2 (split, chunk-padded) + spins ----
    const float2* W2g = (const float2*)W2;
    #pragma unroll
    for (int i = t; i < H_DIM; i += THREADS) {
        const float2 g = W2g[i];
        const int c = i >> 5, k = i & 31;
        W2xs[c * PAD_CH + k] = g.x;
        W2ys[c * PAD_CH + k] = g.y;
    }
    if (t < B_SAMP * D_SITES)
        Xs[t] = x[(size_t)n0 * D_SITES + t];

    // ---- stage E+/E- rows for site 0 into buffer 0 ----
    // 2048 granules: j<1024 -> Ep row, j>=1024 -> Em row (at +CH).
    #pragma unroll
    for (int j = t; j < 2 * H_DIM / 4; j += THREADS) {
        const int tab = j >> 10, jr = j & 1023;
        const float* src = (tab ? g_Em : g_Ep) + 4 * jr;
        cp16(smem_u32 + (uint32_t)(tab * CH + (jr >> 3) * PAD_CH + ((jr & 7) << 2)) * 4u,
             src);
    }
    asm volatile("cp.async.commit_group;");

    // ---- e init: exp2(K*b1) ----
    float e[PER_THR];
    {
        const float4* b1v = (const float4*)(b1 + hp * PER_THR);
        #pragma unroll
        for (int k = 0; k < 8; k++) {
            const float4 v = b1v[k];
            e[4 * k + 0] = fex2(KTANH * v.x);
            e[4 * k + 1] = fex2(KTANH * v.y);
            e[4 * k + 2] = fex2(KTANH * v.z);
            e[4 * k + 3] = fex2(KTANH * v.w);
        }
    }

    asm volatile("cp.async.wait_group 0;" ::: "memory");
    __syncthreads();   // W2/Xs/E rows 0 visible

    const float* WXb = W2xs + hp * PAD_CH;
    const float* WYb = W2ys + hp * PAD_CH;

    // ---- one-time C0/C1 = sum(W2 col) + b2 ----
    float C0 = 0.0f, C1 = 0.0f;
    {
        float sx = 0.0f, sy = 0.0f;
        const float4* wx4 = (const float4*)WXb;
        const float4* wy4 = (const float4*)WYb;
        #pragma unroll
        for (int k = 0; k < 8; k++) {
            const float4 a = wx4[k], bq = wy4[k];
            sx += (a.x + a.y) + (a.z + a.w);
            sy += (bq.x + bq.y) + (bq.z + bq.w);
        }
        #pragma unroll
        for (int o = 16; o; o >>= 1) {
            sx += __shfl_xor_sync(0xffffffffu, sx, o);
            sy += __shfl_xor_sync(0xffffffffu, sy, o);
        }
        if (lane == 0) red[warp] = make_float2(sx, sy);
        __syncthreads();
        if (leader) {
            float a0s = 0.0f, a1s = 0.0f;
            #pragma unroll
            for (int w = 0; w < 4; w++) {
                const float2 v = red[nl * 4 + w];
                a0s += v.x; a1s += v.y;
            }
            C0 = a0s + b2[0];
            C1 = a1s + b2[1];
        }
        __syncthreads();   // red free for the main loop
    }

    float wav = 1.0f;
    int buf = 0;

    for (int d = 0; d < D_SITES; d++) {
        // prefetch E+/E- rows for site d+1 into the other buffer
        if (d + 1 < D_SITES) {
            const int rofs = (d + 1) * H_DIM;
            const uint32_t dbase = smem_u32 + (uint32_t)((buf ^ 1) * 2 * CH) * 4u;
            #pragma unroll
            for (int j = t; j < 2 * H_DIM / 4; j += THREADS) {
                const int tab = j >> 10, jr = j & 1023;
                const float* src = (tab ? g_Em : g_Ep) + rofs + 4 * jr;
                cp16(dbase + (uint32_t)(tab * CH + (jr >> 3) * PAD_CH + ((jr & 7) << 2)) * 4u,
                     src);
            }
        }
        asm volatile("cp.async.commit_group;");

        const float xs = Xs[nl * D_SITES + d];
        // sign select ONCE per site at the pointer level (warp-uniform)
        const float* Eb = Es + buf * 2 * CH + (xs > 0.0f ? 0 : CH) + hp * PAD_CH;

        // two accumulators per output column to shorten FFMA chains
        float d0a = 0.0f, d0b = 0.0f, d1a = 0.0f, d1b = 0.0f;

        #pragma unroll
        for (int q = 0; q < 8; q++) {
            const float4 Ev = *(const float4*)(Eb  + 4 * q);
            const float4 wx = *(const float4*)(WXb + 4 * q);
            const float4 wy = *(const float4*)(WYb + 4 * q);
            const float e0 = e[4 * q + 0];
            const float e1 = e[4 * q + 1];
            const float e2 = e[4 * q + 2];
            const float e3 = e[4 * q + 3];
            const float u0 = e0 + 1.0f;
            const float u1 = e1 + 1.0f;
            const float u2 = e2 + 1.0f;
            const float u3 = e3 + 1.0f;
            // pairwise shared rcp (MUFU is idle now; 3 FMUL + 1 rcp per pair)
            const float rA = frcp(u0 * u1);
            const float q0 = rA * u1;
            const float q1 = rA * u0;
            const float rB = frcp(u2 * u3);
            const float q2 = rB * u3;
            const float q3 = rB * u2;
            d0a = fmaf(q0, wx.x, d0a);
            d0b = fmaf(q1, wx.y, d0b);
            d0a = fmaf(q2, wx.z, d0a);
            d0b = fmaf(q3, wx.w, d0b);
            d1a = fmaf(q0, wy.x, d1a);
            d1b = fmaf(q1, wy.y, d1b);
            d1a = fmaf(q2, wy.z, d1a);
            d1b = fmaf(q3, wy.w, d1b);
            // multiplicative accumulator update (replaces ex2 + FFMA)
            e[4 * q + 0] = e0 * Ev.x;
            e[4 * q + 1] = e1 * Ev.y;
            e[4 * q + 2] = e2 * Ev.z;
            e[4 * q + 3] = e3 * Ev.w;
        }
        float D0 = d0a + d0b;
        float D1 = d1a + d1b;

        #pragma unroll
        for (int o = 16; o; o >>= 1) {
            D0 += __shfl_xor_sync(0xffffffffu, D0, o);
            D1 += __shfl_xor_sync(0xffffffffu, D1, o);
        }
        float2* redb = red + (d & 1) * 16;
        if (lane == 0) redb[warp] = make_float2(D0, D1);

        asm volatile("cp.async.wait_group 0;" ::: "memory");
        __syncthreads();   // publishes red AND next E buffer

        if (leader) {
            const float2 r0 = redb[nl * 4 + 0];
            const float2 r1 = redb[nl * 4 + 1];
            const float2 r2 = redb[nl * 4 + 2];
            const float2 r3 = redb[nl * 4 + 3];
            const float S0 = (r0.x + r1.x) + (r2.x + r3.x);
            const float S1 = (r0.y + r1.y) + (r2.y + r3.y);
            const float z0 = fmaf(-2.0f, S0, C0);
            const float z1 = fmaf(-2.0f, S1, C1);
            const float t0 = tanhf(z0), t1 = tanhf(z1);
            const float nrm = fmaxf(sqrtf(t0 * t0 + t1 * t1), 1e-12f);
            wav *= (xs > 0.0f ? t0 : t1) / nrm;
        }
        buf ^= 1;
    }

    if (leader) out[n0 + nl] = wav;
}

extern "C" void kernel_launch(void* const* d_in, const int* in_sizes, int n_in,
                              void* d_out, int out_size) {
    const float* x  = (const float*)d_in[0];   // [8192,64]
    const float* W1 = (const float*)d_in[1];   // [64,4096]
    const float* b1 = (const float*)d_in[2];   // [4096]
    const float* W2 = (const float*)d_in[3];   // [4096,2]
    const float* b2 = (const float*)d_in[4];   // [2]
    float* out = (float*)d_out;                // [8192]

    // fill E+/E- tables (graph-capturable plain launch; deterministic)
    qnade_prep<<<(D_SITES * H_DIM) / 256, 256>>>(W1);

    const int smem_bytes =
        (6 * CH + B_SAMP * D_SITES) * (int)sizeof(float) + 32 * (int)sizeof(float2);

    cudaFuncSetAttribute(qnade_kernel,
                         cudaFuncAttributeMaxDynamicSharedMemorySize, smem_bytes);

    qnade_kernel<<<N_SAMP / B_SAMP, THREADS, smem_bytes>>>(x, b1, W2, b2, out);
}